// round 7
// baseline (speedup 1.0000x reference)
#include <cuda_runtime.h>
#include <math.h>

#define D_DIM 300

__device__ __forceinline__ void fma16(float* acc, const float4 w, const float4 v) {
    acc[0]  = fmaf(w.x, v.x, acc[0]);
    acc[1]  = fmaf(w.x, v.y, acc[1]);
    acc[2]  = fmaf(w.x, v.z, acc[2]);
    acc[3]  = fmaf(w.x, v.w, acc[3]);
    acc[4]  = fmaf(w.y, v.x, acc[4]);
    acc[5]  = fmaf(w.y, v.y, acc[5]);
    acc[6]  = fmaf(w.y, v.z, acc[6]);
    acc[7]  = fmaf(w.y, v.w, acc[7]);
    acc[8]  = fmaf(w.z, v.x, acc[8]);
    acc[9]  = fmaf(w.z, v.y, acc[9]);
    acc[10] = fmaf(w.z, v.z, acc[10]);
    acc[11] = fmaf(w.z, v.w, acc[11]);
    acc[12] = fmaf(w.w, v.x, acc[12]);
    acc[13] = fmaf(w.w, v.y, acc[13]);
    acc[14] = fmaf(w.w, v.z, acc[14]);
    acc[15] = fmaf(w.w, v.w, acc[15]);
}

__global__ __launch_bounds__(256, 8)
void multisense_kernel(const float4* __restrict__ V4,    // [VOCAB * D] float4 (senses innermost)
                       const float4* __restrict__ W4,    // [COVOCAB * D]
                       const float4* __restrict__ vb4,   // [VOCAB]
                       const float4* __restrict__ wb4,   // [COVOCAB]
                       const int* __restrict__ IJ,       // [B*2] int32
                       float* __restrict__ out,
                       int B)
{
    const int warp_id = blockIdx.x * (blockDim.x >> 5) + (threadIdx.x >> 5);
    if (warp_id >= B) return;
    const int lane = threadIdx.x & 31;

    const int i = __ldg(IJ + 2 * warp_id);
    const int j = __ldg(IJ + 2 * warp_id + 1);

    const float4* __restrict__ Vr = V4 + (long long)i * D_DIM;
    const float4* __restrict__ Wr = W4 + (long long)j * D_DIM;

    // acc[s*4+t] = sum_d W[j,d,s] * V[i,d,t]
    float acc[16];
#pragma unroll
    for (int k = 0; k < 16; k++) acc[k] = 0.0f;

    // Unroll x2: 4 independent LDG.128 issued per iteration -> 2x in-flight bytes.
#pragma unroll 1
    for (int k = 0; k < 4; k++) {
        const int d = lane + 64 * k;          // d in [0, 255]
        const float4 v1 = __ldg(Vr + d);
        const float4 w1 = __ldg(Wr + d);
        const float4 v2 = __ldg(Vr + d + 32);
        const float4 w2 = __ldg(Wr + d + 32);
        fma16(acc, w1, v1);
        fma16(acc, w2, v2);
    }
    {
        // d = lane+256 always < 300; d = lane+288 valid only for lane < 12.
        const int d = lane + 256;
        const float4 v1 = __ldg(Vr + d);
        const float4 w1 = __ldg(Wr + d);
        float4 v2 = make_float4(0.f, 0.f, 0.f, 0.f);
        float4 w2 = make_float4(0.f, 0.f, 0.f, 0.f);
        if (lane < 12) {
            v2 = __ldg(Vr + d + 32);
            w2 = __ldg(Wr + d + 32);
        }
        fma16(acc, w1, v1);
        fma16(acc, w2, v2);
    }

    // Warp butterfly reduction: every lane ends with the full 16 sums.
#pragma unroll
    for (int off = 16; off > 0; off >>= 1) {
#pragma unroll
        for (int k = 0; k < 16; k++)
            acc[k] += __shfl_xor_sync(0xffffffffu, acc[k], off);
    }

    if (lane == 0) {
        const float4 wb = __ldg(wb4 + j);  // bias over s
        const float4 vb = __ldg(vb4 + i);  // bias over t
        const float bs[4] = {wb.x, wb.y, wb.z, wb.w};
        const float bt[4] = {vb.x, vb.y, vb.z, vb.w};

        float vals[16];
        float m = -INFINITY;
#pragma unroll
        for (int s = 0; s < 4; s++) {
#pragma unroll
            for (int t = 0; t < 4; t++) {
                const float x = acc[s * 4 + t] + bs[s] + bt[t];
                vals[s * 4 + t] = x;
                m = fmaxf(m, x);
            }
        }
        float sum = 0.0f;
#pragma unroll
        for (int k = 0; k < 16; k++)
            sum += __expf(vals[k] - m);
        out[warp_id] = __logf(sum) + m;
    }
}

extern "C" void kernel_launch(void* const* d_in, const int* in_sizes, int n_in,
                              void* d_out, int out_size)
{
    const float4* V4      = (const float4*)d_in[0];
    const float4* W4      = (const float4*)d_in[1];
    const float4* vb4     = (const float4*)d_in[2];
    const float4* wb4     = (const float4*)d_in[3];
    const int* IJ         = (const int*)d_in[4];
    float* out            = (float*)d_out;

    const int B = in_sizes[4] / 2;  // IJ has B*2 elements

    const int warps_per_block = 8;           // 256 threads
    const int blocks = (B + warps_per_block - 1) / warps_per_block;
    multisense_kernel<<<blocks, warps_per_block * 32>>>(V4, W4, vb4, wb4, IJ, out, B);
}

// round 8
// speedup vs baseline: 1.0719x; 1.0719x over previous
#include <cuda_runtime.h>
#include <math.h>

#define D_DIM 300
#define VOCAB_SZ 50000
#define MAX_B (1 << 20)
#define SCAN_THREADS 1024
#define SCAN_CHUNK ((VOCAB_SZ + SCAN_THREADS - 1) / SCAN_THREADS)  // 49

__device__ int g_counts[VOCAB_SZ];   // bucket counts -> cursors
__device__ int g_perm[MAX_B];        // sorted pair indices

// ---------------- sort pipeline ----------------

__global__ void zero_counts_kernel() {
    int idx = blockIdx.x * blockDim.x + threadIdx.x;
    if (idx < VOCAB_SZ) g_counts[idx] = 0;
}

__global__ void count_kernel(const int* __restrict__ IJ, int B) {
    int p = blockIdx.x * blockDim.x + threadIdx.x;
    if (p < B) atomicAdd(&g_counts[__ldg(IJ + 2 * p)], 1);
}

__global__ void scan_kernel() {
    __shared__ int sums[SCAN_THREADS];
    const int t = threadIdx.x;
    const int base = t * SCAN_CHUNK;

    int local = 0;
#pragma unroll 1
    for (int e = 0; e < SCAN_CHUNK; e++) {
        int idx = base + e;
        if (idx < VOCAB_SZ) local += g_counts[idx];
    }
    sums[t] = local;
    __syncthreads();

    // Hillis-Steele inclusive scan over thread partials
    for (int off = 1; off < SCAN_THREADS; off <<= 1) {
        int v = (t >= off) ? sums[t - off] : 0;
        __syncthreads();
        sums[t] += v;
        __syncthreads();
    }

    int running = (t == 0) ? 0 : sums[t - 1];  // exclusive prefix for this chunk
#pragma unroll 1
    for (int e = 0; e < SCAN_CHUNK; e++) {
        int idx = base + e;
        if (idx < VOCAB_SZ) {
            int c = g_counts[idx];
            g_counts[idx] = running;   // becomes bucket cursor
            running += c;
        }
    }
}

__global__ void scatter_kernel(const int* __restrict__ IJ, int B) {
    int p = blockIdx.x * blockDim.x + threadIdx.x;
    if (p < B) {
        int i = __ldg(IJ + 2 * p);
        int pos = atomicAdd(&g_counts[i], 1);
        g_perm[pos] = p;
    }
}

// ---------------- main kernel (R5-proven body, permuted order) ----------------

__device__ __forceinline__ void fma16(float* acc, const float4 w, const float4 v) {
    acc[0]  = fmaf(w.x, v.x, acc[0]);
    acc[1]  = fmaf(w.x, v.y, acc[1]);
    acc[2]  = fmaf(w.x, v.z, acc[2]);
    acc[3]  = fmaf(w.x, v.w, acc[3]);
    acc[4]  = fmaf(w.y, v.x, acc[4]);
    acc[5]  = fmaf(w.y, v.y, acc[5]);
    acc[6]  = fmaf(w.y, v.z, acc[6]);
    acc[7]  = fmaf(w.y, v.w, acc[7]);
    acc[8]  = fmaf(w.z, v.x, acc[8]);
    acc[9]  = fmaf(w.z, v.y, acc[9]);
    acc[10] = fmaf(w.z, v.z, acc[10]);
    acc[11] = fmaf(w.z, v.w, acc[11]);
    acc[12] = fmaf(w.w, v.x, acc[12]);
    acc[13] = fmaf(w.w, v.y, acc[13]);
    acc[14] = fmaf(w.w, v.z, acc[14]);
    acc[15] = fmaf(w.w, v.w, acc[15]);
}

__global__ __launch_bounds__(256, 8)
void multisense_kernel(const float4* __restrict__ V4,
                       const float4* __restrict__ W4,
                       const float4* __restrict__ vb4,
                       const float4* __restrict__ wb4,
                       const int* __restrict__ IJ,
                       float* __restrict__ out,
                       int B)
{
    const int warp_id = blockIdx.x * (blockDim.x >> 5) + (threadIdx.x >> 5);
    if (warp_id >= B) return;
    const int lane = threadIdx.x & 31;

    const int p = __ldg(g_perm + warp_id);
    const int i = __ldg(IJ + 2 * p);
    const int j = __ldg(IJ + 2 * p + 1);

    const float4* __restrict__ Vr = V4 + (long long)i * D_DIM;
    const float4* __restrict__ Wr = W4 + (long long)j * D_DIM;

    float acc[16];
#pragma unroll
    for (int k = 0; k < 16; k++) acc[k] = 0.0f;

#pragma unroll 1
    for (int d = lane; d < D_DIM; d += 32) {
        const float4 v = __ldg(Vr + d);
        const float4 w = __ldg(Wr + d);
        fma16(acc, w, v);
    }

#pragma unroll
    for (int off = 16; off > 0; off >>= 1) {
#pragma unroll
        for (int k = 0; k < 16; k++)
            acc[k] += __shfl_xor_sync(0xffffffffu, acc[k], off);
    }

    if (lane == 0) {
        const float4 wb = __ldg(wb4 + j);
        const float4 vb = __ldg(vb4 + i);
        const float bs[4] = {wb.x, wb.y, wb.z, wb.w};
        const float bt[4] = {vb.x, vb.y, vb.z, vb.w};

        float vals[16];
        float m = -INFINITY;
#pragma unroll
        for (int s = 0; s < 4; s++) {
#pragma unroll
            for (int t = 0; t < 4; t++) {
                const float x = acc[s * 4 + t] + bs[s] + bt[t];
                vals[s * 4 + t] = x;
                m = fmaxf(m, x);
            }
        }
        float sum = 0.0f;
#pragma unroll
        for (int k = 0; k < 16; k++)
            sum += __expf(vals[k] - m);
        out[p] = __logf(sum) + m;
    }
}

extern "C" void kernel_launch(void* const* d_in, const int* in_sizes, int n_in,
                              void* d_out, int out_size)
{
    const float4* V4      = (const float4*)d_in[0];
    const float4* W4      = (const float4*)d_in[1];
    const float4* vb4     = (const float4*)d_in[2];
    const float4* wb4     = (const float4*)d_in[3];
    const int* IJ         = (const int*)d_in[4];
    float* out            = (float*)d_out;

    const int B = in_sizes[4] / 2;

    const int t = 256;
    zero_counts_kernel<<<(VOCAB_SZ + t - 1) / t, t>>>();
    count_kernel<<<(B + t - 1) / t, t>>>(IJ, B);
    scan_kernel<<<1, SCAN_THREADS>>>();
    scatter_kernel<<<(B + t - 1) / t, t>>>(IJ, B);

    const int warps_per_block = 8;
    const int blocks = (B + warps_per_block - 1) / warps_per_block;
    multisense_kernel<<<blocks, warps_per_block * 32>>>(V4, W4, vb4, wb4, IJ, out, B);
}

// round 9
// speedup vs baseline: 1.2138x; 1.1324x over previous
#include <cuda_runtime.h>
#include <math.h>

#define D_DIM 300
#define VOCAB_SZ 50000
#define MAX_B (1 << 20)
#define NB ((VOCAB_SZ + 255) / 256)   // 196 scan blocks

__device__ int g_counts[VOCAB_SZ];    // bucket counts -> cursors
__device__ int g_block_sums[NB];
__device__ int g_perm[MAX_B];

// ---------------- sort pipeline (all parallel, ~8us total) ----------------

__global__ void zero_counts_kernel() {
    int idx = blockIdx.x * blockDim.x + threadIdx.x;
    if (idx < VOCAB_SZ) g_counts[idx] = 0;
}

__global__ void count_kernel(const int* __restrict__ IJ, int B) {
    int p = blockIdx.x * blockDim.x + threadIdx.x;
    if (p < B) atomicAdd(&g_counts[__ldg(IJ + 2 * p)], 1);
}

__global__ void block_sum_kernel() {
    __shared__ int sh[256];
    const int t = threadIdx.x;
    const int idx = blockIdx.x * 256 + t;
    sh[t] = (idx < VOCAB_SZ) ? g_counts[idx] : 0;
    __syncthreads();
    for (int off = 128; off > 0; off >>= 1) {
        if (t < off) sh[t] += sh[t + off];
        __syncthreads();
    }
    if (t == 0) g_block_sums[blockIdx.x] = sh[0];
}

__global__ void top_scan_kernel() {
    __shared__ int sh[256];
    const int t = threadIdx.x;
    int v = (t < NB) ? g_block_sums[t] : 0;
    sh[t] = v;
    __syncthreads();
    for (int off = 1; off < 256; off <<= 1) {
        int add = (t >= off) ? sh[t - off] : 0;
        __syncthreads();
        sh[t] += add;
        __syncthreads();
    }
    if (t < NB) g_block_sums[t] = (t == 0) ? 0 : sh[t - 1];  // exclusive
}

__global__ void downsweep_kernel() {
    __shared__ int sh[256];
    const int t = threadIdx.x;
    const int idx = blockIdx.x * 256 + t;
    int v = (idx < VOCAB_SZ) ? g_counts[idx] : 0;
    sh[t] = v;
    __syncthreads();
    for (int off = 1; off < 256; off <<= 1) {
        int add = (t >= off) ? sh[t - off] : 0;
        __syncthreads();
        sh[t] += add;
        __syncthreads();
    }
    if (idx < VOCAB_SZ) {
        int excl = (t == 0) ? 0 : sh[t - 1];
        g_counts[idx] = excl + g_block_sums[blockIdx.x];  // bucket cursor
    }
}

__global__ void scatter_kernel(const int* __restrict__ IJ, int B) {
    int p = blockIdx.x * blockDim.x + threadIdx.x;
    if (p < B) {
        int i = __ldg(IJ + 2 * p);
        int pos = atomicAdd(&g_counts[i], 1);
        g_perm[pos] = p;
    }
}

// ---------------- main kernel: unroll x2, NO occupancy cap ----------------

__device__ __forceinline__ void fma16(float* acc, const float4 w, const float4 v) {
    acc[0]  = fmaf(w.x, v.x, acc[0]);
    acc[1]  = fmaf(w.x, v.y, acc[1]);
    acc[2]  = fmaf(w.x, v.z, acc[2]);
    acc[3]  = fmaf(w.x, v.w, acc[3]);
    acc[4]  = fmaf(w.y, v.x, acc[4]);
    acc[5]  = fmaf(w.y, v.y, acc[5]);
    acc[6]  = fmaf(w.y, v.z, acc[6]);
    acc[7]  = fmaf(w.y, v.w, acc[7]);
    acc[8]  = fmaf(w.z, v.x, acc[8]);
    acc[9]  = fmaf(w.z, v.y, acc[9]);
    acc[10] = fmaf(w.z, v.z, acc[10]);
    acc[11] = fmaf(w.z, v.w, acc[11]);
    acc[12] = fmaf(w.w, v.x, acc[12]);
    acc[13] = fmaf(w.w, v.y, acc[13]);
    acc[14] = fmaf(w.w, v.z, acc[14]);
    acc[15] = fmaf(w.w, v.w, acc[15]);
}

__global__ __launch_bounds__(256)
void multisense_kernel(const float4* __restrict__ V4,
                       const float4* __restrict__ W4,
                       const float4* __restrict__ vb4,
                       const float4* __restrict__ wb4,
                       const int* __restrict__ IJ,
                       float* __restrict__ out,
                       int B)
{
    const int warp_id = blockIdx.x * (blockDim.x >> 5) + (threadIdx.x >> 5);
    if (warp_id >= B) return;
    const int lane = threadIdx.x & 31;

    const int p = __ldg(g_perm + warp_id);
    const int i = __ldg(IJ + 2 * p);
    const int j = __ldg(IJ + 2 * p + 1);

    const float4* __restrict__ Vr = V4 + (long long)i * D_DIM;
    const float4* __restrict__ Wr = W4 + (long long)j * D_DIM;

    float acc[16];
#pragma unroll
    for (int k = 0; k < 16; k++) acc[k] = 0.0f;

    // 4 independent LDG.128 per iteration; d = lane + 32*{0..9}, k=9 only lane<12.
#pragma unroll 1
    for (int k = 0; k < 4; k++) {
        const int d = lane + 64 * k;          // covers d in [0, 255]
        const float4 v1 = __ldg(Vr + d);
        const float4 w1 = __ldg(Wr + d);
        const float4 v2 = __ldg(Vr + d + 32);
        const float4 w2 = __ldg(Wr + d + 32);
        fma16(acc, w1, v1);
        fma16(acc, w2, v2);
    }
    {
        const int d = lane + 256;             // always < 300
        const float4 v1 = __ldg(Vr + d);
        const float4 w1 = __ldg(Wr + d);
        float4 v2 = make_float4(0.f, 0.f, 0.f, 0.f);
        float4 w2 = make_float4(0.f, 0.f, 0.f, 0.f);
        if (lane < 12) {                      // d+32 in [288, 299]
            v2 = __ldg(Vr + d + 32);
            w2 = __ldg(Wr + d + 32);
        }
        fma16(acc, w1, v1);
        fma16(acc, w2, v2);
    }

#pragma unroll
    for (int off = 16; off > 0; off >>= 1) {
#pragma unroll
        for (int k = 0; k < 16; k++)
            acc[k] += __shfl_xor_sync(0xffffffffu, acc[k], off);
    }

    if (lane == 0) {
        const float4 wb = __ldg(wb4 + j);
        const float4 vb = __ldg(vb4 + i);
        const float bs[4] = {wb.x, wb.y, wb.z, wb.w};
        const float bt[4] = {vb.x, vb.y, vb.z, vb.w};

        float vals[16];
        float m = -INFINITY;
#pragma unroll
        for (int s = 0; s < 4; s++) {
#pragma unroll
            for (int t = 0; t < 4; t++) {
                const float x = acc[s * 4 + t] + bs[s] + bt[t];
                vals[s * 4 + t] = x;
                m = fmaxf(m, x);
            }
        }
        float sum = 0.0f;
#pragma unroll
        for (int k = 0; k < 16; k++)
            sum += __expf(vals[k] - m);
        out[p] = __logf(sum) + m;
    }
}

extern "C" void kernel_launch(void* const* d_in, const int* in_sizes, int n_in,
                              void* d_out, int out_size)
{
    const float4* V4      = (const float4*)d_in[0];
    const float4* W4      = (const float4*)d_in[1];
    const float4* vb4     = (const float4*)d_in[2];
    const float4* wb4     = (const float4*)d_in[3];
    const int* IJ         = (const int*)d_in[4];
    float* out            = (float*)d_out;

    const int B = in_sizes[4] / 2;

    const int t = 256;
    zero_counts_kernel<<<(VOCAB_SZ + t - 1) / t, t>>>();
    count_kernel<<<(B + t - 1) / t, t>>>(IJ, B);
    block_sum_kernel<<<NB, 256>>>();
    top_scan_kernel<<<1, 256>>>();
    downsweep_kernel<<<NB, 256>>>();
    scatter_kernel<<<(B + t - 1) / t, t>>>(IJ, B);

    const int warps_per_block = 8;
    const int blocks = (B + warps_per_block - 1) / warps_per_block;
    multisense_kernel<<<blocks, warps_per_block * 32>>>(V4, W4, vb4, wb4, IJ, out, B);
}

// round 10
// speedup vs baseline: 1.2182x; 1.0036x over previous
#include <cuda_runtime.h>
#include <math.h>

#define D_DIM 300

__device__ __forceinline__ void fma16(float* acc, const float4 w, const float4 v) {
    acc[0]  = fmaf(w.x, v.x, acc[0]);
    acc[1]  = fmaf(w.x, v.y, acc[1]);
    acc[2]  = fmaf(w.x, v.z, acc[2]);
    acc[3]  = fmaf(w.x, v.w, acc[3]);
    acc[4]  = fmaf(w.y, v.x, acc[4]);
    acc[5]  = fmaf(w.y, v.y, acc[5]);
    acc[6]  = fmaf(w.y, v.z, acc[6]);
    acc[7]  = fmaf(w.y, v.w, acc[7]);
    acc[8]  = fmaf(w.z, v.x, acc[8]);
    acc[9]  = fmaf(w.z, v.y, acc[9]);
    acc[10] = fmaf(w.z, v.z, acc[10]);
    acc[11] = fmaf(w.z, v.w, acc[11]);
    acc[12] = fmaf(w.w, v.x, acc[12]);
    acc[13] = fmaf(w.w, v.y, acc[13]);
    acc[14] = fmaf(w.w, v.z, acc[14]);
    acc[15] = fmaf(w.w, v.w, acc[15]);
}

// NOTE: no min-blocks clause — R6 showed __launch_bounds__(256, 8)'s 32-reg cap
// serializes the 4-load body (L1 replays). Let ptxas take ~56 regs.
__global__ __launch_bounds__(256)
void multisense_kernel(const float4* __restrict__ V4,    // [VOCAB * D] float4 (senses innermost)
                       const float4* __restrict__ W4,    // [COVOCAB * D]
                       const float4* __restrict__ vb4,   // [VOCAB]
                       const float4* __restrict__ wb4,   // [COVOCAB]
                       const int* __restrict__ IJ,       // [B*2] int32
                       float* __restrict__ out,
                       int B)
{
    const int warp_id = blockIdx.x * (blockDim.x >> 5) + (threadIdx.x >> 5);
    if (warp_id >= B) return;
    const int lane = threadIdx.x & 31;

    const int i = __ldg(IJ + 2 * warp_id);
    const int j = __ldg(IJ + 2 * warp_id + 1);

    const float4* __restrict__ Vr = V4 + (long long)i * D_DIM;
    const float4* __restrict__ Wr = W4 + (long long)j * D_DIM;

    // acc[s*4+t] = sum_d W[j,d,s] * V[i,d,t]
    float acc[16];
#pragma unroll
    for (int k = 0; k < 16; k++) acc[k] = 0.0f;

    // 4 independent LDG.128 per iteration -> ~2x in-flight bytes vs rolled loop.
#pragma unroll 1
    for (int k = 0; k < 4; k++) {
        const int d = lane + 64 * k;          // covers d in [0, 255]
        const float4 v1 = __ldg(Vr + d);
        const float4 w1 = __ldg(Wr + d);
        const float4 v2 = __ldg(Vr + d + 32);
        const float4 w2 = __ldg(Wr + d + 32);
        fma16(acc, w1, v1);
        fma16(acc, w2, v2);
    }
    {
        const int d = lane + 256;             // always < 300
        const float4 v1 = __ldg(Vr + d);
        const float4 w1 = __ldg(Wr + d);
        float4 v2 = make_float4(0.f, 0.f, 0.f, 0.f);
        float4 w2 = make_float4(0.f, 0.f, 0.f, 0.f);
        if (lane < 12) {                      // d+32 in [288, 299]
            v2 = __ldg(Vr + d + 32);
            w2 = __ldg(Wr + d + 32);
        }
        fma16(acc, w1, v1);
        fma16(acc, w2, v2);
    }

    // Warp butterfly reduction: every lane ends with the full 16 sums.
#pragma unroll
    for (int off = 16; off > 0; off >>= 1) {
#pragma unroll
        for (int k = 0; k < 16; k++)
            acc[k] += __shfl_xor_sync(0xffffffffu, acc[k], off);
    }

    if (lane == 0) {
        const float4 wb = __ldg(wb4 + j);  // bias over s
        const float4 vb = __ldg(vb4 + i);  // bias over t
        const float bs[4] = {wb.x, wb.y, wb.z, wb.w};
        const float bt[4] = {vb.x, vb.y, vb.z, vb.w};

        float vals[16];
        float m = -INFINITY;
#pragma unroll
        for (int s = 0; s < 4; s++) {
#pragma unroll
            for (int t = 0; t < 4; t++) {
                const float x = acc[s * 4 + t] + bs[s] + bt[t];
                vals[s * 4 + t] = x;
                m = fmaxf(m, x);
            }
        }
        float sum = 0.0f;
#pragma unroll
        for (int k = 0; k < 16; k++)
            sum += __expf(vals[k] - m);
        out[warp_id] = __logf(sum) + m;
    }
}

extern "C" void kernel_launch(void* const* d_in, const int* in_sizes, int n_in,
                              void* d_out, int out_size)
{
    const float4* V4      = (const float4*)d_in[0];
    const float4* W4      = (const float4*)d_in[1];
    const float4* vb4     = (const float4*)d_in[2];
    const float4* wb4     = (const float4*)d_in[3];
    const int* IJ         = (const int*)d_in[4];
    float* out            = (float*)d_out;

    const int B = in_sizes[4] / 2;  // IJ has B*2 elements

    const int warps_per_block = 8;           // 256 threads
    const int blocks = (B + warps_per_block - 1) / warps_per_block;
    multisense_kernel<<<blocks, warps_per_block * 32>>>(V4, W4, vb4, wb4, IJ, out, B);
}

// round 12
// speedup vs baseline: 1.3248x; 1.0875x over previous
#include <cuda_runtime.h>
#include <math.h>

#define D_DIM 300
#define VOCAB_SZ 50000
#define BUCKET_SHIFT 4
#define NBUCK (VOCAB_SZ >> BUCKET_SHIFT)   // 3125 buckets, ~32 pairs each
#define MAX_B (1 << 20)
#define SCAN_T 1024
#define SCAN_PER ((NBUCK + SCAN_T - 1) / SCAN_T)  // 4

__device__ int g_counts[NBUCK];   // bucket counts -> cursors (memset to 0 each launch)
__device__ int g_perm[MAX_B];

// ---------------- lean bucket-sort pipeline ----------------

__global__ void count_kernel(const int* __restrict__ IJ, int B) {
    int p = blockIdx.x * blockDim.x + threadIdx.x;
    if (p < B) atomicAdd(&g_counts[__ldg(IJ + 2 * p) >> BUCKET_SHIFT], 1);
}

__global__ void scan_kernel() {
    __shared__ int sums[SCAN_T];
    const int t = threadIdx.x;
    const int base = t * SCAN_PER;

    int local[SCAN_PER];
    int tot = 0;
#pragma unroll
    for (int e = 0; e < SCAN_PER; e++) {
        int idx = base + e;
        local[e] = (idx < NBUCK) ? g_counts[idx] : 0;
        tot += local[e];
    }
    sums[t] = tot;
    __syncthreads();
    // Hillis-Steele inclusive scan over per-thread totals
    for (int off = 1; off < SCAN_T; off <<= 1) {
        int v = (t >= off) ? sums[t - off] : 0;
        __syncthreads();
        sums[t] += v;
        __syncthreads();
    }
    int running = (t == 0) ? 0 : sums[t - 1];   // exclusive prefix
#pragma unroll
    for (int e = 0; e < SCAN_PER; e++) {
        int idx = base + e;
        if (idx < NBUCK) {
            g_counts[idx] = running;            // becomes bucket cursor
            running += local[e];
        }
    }
}

__global__ void scatter_kernel(const int* __restrict__ IJ, int B) {
    int p = blockIdx.x * blockDim.x + threadIdx.x;
    if (p < B) {
        int b = __ldg(IJ + 2 * p) >> BUCKET_SHIFT;
        int pos = atomicAdd(&g_counts[b], 1);
        g_perm[pos] = p;
    }
}

// ---------------- main kernel: R5-proven rolled body, permuted order ----------------

__global__ __launch_bounds__(256, 8)
void multisense_kernel(const float4* __restrict__ V4,
                       const float4* __restrict__ W4,
                       const float4* __restrict__ vb4,
                       const float4* __restrict__ wb4,
                       const int* __restrict__ IJ,
                       float* __restrict__ out,
                       int B)
{
    const int warp_id = blockIdx.x * (blockDim.x >> 5) + (threadIdx.x >> 5);
    if (warp_id >= B) return;
    const int lane = threadIdx.x & 31;

    const int p = __ldg(g_perm + warp_id);
    const int i = __ldg(IJ + 2 * p);
    const int j = __ldg(IJ + 2 * p + 1);

    const float4* __restrict__ Vr = V4 + (long long)i * D_DIM;
    const float4* __restrict__ Wr = W4 + (long long)j * D_DIM;

    float acc[16];
#pragma unroll
    for (int k = 0; k < 16; k++) acc[k] = 0.0f;

#pragma unroll 1
    for (int d = lane; d < D_DIM; d += 32) {
        const float4 v = __ldg(Vr + d);
        const float4 w = __ldg(Wr + d);
        acc[0]  = fmaf(w.x, v.x, acc[0]);
        acc[1]  = fmaf(w.x, v.y, acc[1]);
        acc[2]  = fmaf(w.x, v.z, acc[2]);
        acc[3]  = fmaf(w.x, v.w, acc[3]);
        acc[4]  = fmaf(w.y, v.x, acc[4]);
        acc[5]  = fmaf(w.y, v.y, acc[5]);
        acc[6]  = fmaf(w.y, v.z, acc[6]);
        acc[7]  = fmaf(w.y, v.w, acc[7]);
        acc[8]  = fmaf(w.z, v.x, acc[8]);
        acc[9]  = fmaf(w.z, v.y, acc[9]);
        acc[10] = fmaf(w.z, v.z, acc[10]);
        acc[11] = fmaf(w.z, v.w, acc[11]);
        acc[12] = fmaf(w.w, v.x, acc[12]);
        acc[13] = fmaf(w.w, v.y, acc[13]);
        acc[14] = fmaf(w.w, v.z, acc[14]);
        acc[15] = fmaf(w.w, v.w, acc[15]);
    }

#pragma unroll
    for (int off = 16; off > 0; off >>= 1) {
#pragma unroll
        for (int k = 0; k < 16; k++)
            acc[k] += __shfl_xor_sync(0xffffffffu, acc[k], off);
    }

    if (lane == 0) {
        const float4 wb = __ldg(wb4 + j);
        const float4 vb = __ldg(vb4 + i);
        const float bs[4] = {wb.x, wb.y, wb.z, wb.w};
        const float bt[4] = {vb.x, vb.y, vb.z, vb.w};

        float vals[16];
        float m = -INFINITY;
#pragma unroll
        for (int s = 0; s < 4; s++) {
#pragma unroll
            for (int t = 0; t < 4; t++) {
                const float x = acc[s * 4 + t] + bs[s] + bt[t];
                vals[s * 4 + t] = x;
                m = fmaxf(m, x);
            }
        }
        float sum = 0.0f;
#pragma unroll
        for (int k = 0; k < 16; k++)
            sum += __expf(vals[k] - m);
        out[p] = __logf(sum) + m;
    }
}

extern "C" void kernel_launch(void* const* d_in, const int* in_sizes, int n_in,
                              void* d_out, int out_size)
{
    const float4* V4      = (const float4*)d_in[0];
    const float4* W4      = (const float4*)d_in[1];
    const float4* vb4     = (const float4*)d_in[2];
    const float4* wb4     = (const float4*)d_in[3];
    const int* IJ         = (const int*)d_in[4];
    float* out            = (float*)d_out;

    const int B = in_sizes[4] / 2;

    // Zero bucket counters via a memset node (cheaper than a kernel launch).
    void* counts_ptr = nullptr;
    cudaGetSymbolAddress(&counts_ptr, g_counts);
    cudaMemsetAsync(counts_ptr, 0, NBUCK * sizeof(int), 0);

    const int t = 256;
    count_kernel<<<(B + t - 1) / t, t>>>(IJ, B);
    scan_kernel<<<1, SCAN_T>>>();
    scatter_kernel<<<(B + t - 1) / t, t>>>(IJ, B);

    const int warps_per_block = 8;
    const int blocks = (B + warps_per_block - 1) / warps_per_block;
    multisense_kernel<<<blocks, warps_per_block * 32>>>(V4, W4, vb4, wb4, IJ, out, B);
}

// round 13
// speedup vs baseline: 1.3444x; 1.0148x over previous
#include <cuda_runtime.h>
#include <cstdint>
#include <math.h>

#define D_DIM 300
#define ROW_BYTES (D_DIM * 16)        // 4800 B per row of float4
#define VOCAB_SZ 50000
#define BUCKET_SHIFT 4
#define NBUCK (VOCAB_SZ >> BUCKET_SHIFT)   // 3125 buckets
#define MAX_B (1 << 20)
#define SCAN_T 1024
#define SCAN_PER ((NBUCK + SCAN_T - 1) / SCAN_T)  // 4
#define WARPS_CTA 4

__device__ int g_counts[NBUCK];
__device__ int g_perm[MAX_B];

// ---------------- lean bucket-sort pipeline (proven in R12) ----------------

__global__ void count_kernel(const int* __restrict__ IJ, int B) {
    int p = blockIdx.x * blockDim.x + threadIdx.x;
    if (p < B) atomicAdd(&g_counts[__ldg(IJ + 2 * p) >> BUCKET_SHIFT], 1);
}

__global__ void scan_kernel() {
    __shared__ int sums[SCAN_T];
    const int t = threadIdx.x;
    const int base = t * SCAN_PER;
    int local[SCAN_PER];
    int tot = 0;
#pragma unroll
    for (int e = 0; e < SCAN_PER; e++) {
        int idx = base + e;
        local[e] = (idx < NBUCK) ? g_counts[idx] : 0;
        tot += local[e];
    }
    sums[t] = tot;
    __syncthreads();
    for (int off = 1; off < SCAN_T; off <<= 1) {
        int v = (t >= off) ? sums[t - off] : 0;
        __syncthreads();
        sums[t] += v;
        __syncthreads();
    }
    int running = (t == 0) ? 0 : sums[t - 1];
#pragma unroll
    for (int e = 0; e < SCAN_PER; e++) {
        int idx = base + e;
        if (idx < NBUCK) {
            g_counts[idx] = running;
            running += local[e];
        }
    }
}

__global__ void scatter_kernel(const int* __restrict__ IJ, int B) {
    int p = blockIdx.x * blockDim.x + threadIdx.x;
    if (p < B) {
        int b = __ldg(IJ + 2 * p) >> BUCKET_SHIFT;
        int pos = atomicAdd(&g_counts[b], 1);
        g_perm[pos] = p;
    }
}

// ---------------- main kernel: cp.async.bulk staging, smem compute ----------------

__device__ __forceinline__ uint32_t smem_u32(const void* p) {
    uint32_t a;
    asm("{ .reg .u64 t; cvta.to.shared.u64 t, %1; cvt.u32.u64 %0, t; }" : "=r"(a) : "l"(p));
    return a;
}

__global__ __launch_bounds__(WARPS_CTA * 32)
void multisense_kernel(const char* __restrict__ Vb,   // V as bytes, row = i*ROW_BYTES
                       const char* __restrict__ Wb,
                       const float4* __restrict__ vb4,
                       const float4* __restrict__ wb4,
                       const int* __restrict__ IJ,
                       float* __restrict__ out,
                       int B)
{
    __shared__ alignas(16) char buf[WARPS_CTA][2 * ROW_BYTES];  // V row then W row
    __shared__ alignas(8) uint64_t mbar[WARPS_CTA];

    const int wid  = threadIdx.x >> 5;
    const int lane = threadIdx.x & 31;
    const int warp_id = blockIdx.x * WARPS_CTA + wid;
    if (warp_id >= B) return;

    const uint32_t mb   = smem_u32(&mbar[wid]);
    const uint32_t base = smem_u32(&buf[wid][0]);

    int p = 0, i = 0, j = 0;
    if (lane == 0) {
        p = __ldg(g_perm + warp_id);
        i = __ldg(IJ + 2 * p);
        j = __ldg(IJ + 2 * p + 1);
        asm volatile("mbarrier.init.shared.b64 [%0], 1;" :: "r"(mb) : "memory");
        asm volatile("fence.proxy.async.shared::cta;" ::: "memory");
    }
    __syncwarp();
    if (lane == 0) {
        asm volatile("mbarrier.arrive.expect_tx.shared.b64 _, [%0], %1;"
                     :: "r"(mb), "r"(2 * ROW_BYTES) : "memory");
        const char* vsrc = Vb + (long long)i * ROW_BYTES;
        const char* wsrc = Wb + (long long)j * ROW_BYTES;
        asm volatile("cp.async.bulk.shared::cta.global.mbarrier::complete_tx::bytes [%0], [%1], %2, [%3];"
                     :: "r"(base), "l"(vsrc), "r"((uint32_t)ROW_BYTES), "r"(mb) : "memory");
        asm volatile("cp.async.bulk.shared::cta.global.mbarrier::complete_tx::bytes [%0], [%1], %2, [%3];"
                     :: "r"(base + ROW_BYTES), "l"(wsrc), "r"((uint32_t)ROW_BYTES), "r"(mb) : "memory");
    }
    // Wait for both rows (phase 0, acquire).
    {
        uint32_t done;
        asm volatile(
            "{\n\t.reg .pred P;\n\t"
            "mbarrier.try_wait.parity.acquire.cta.shared::cta.b64 P, [%1], 0;\n\t"
            "selp.b32 %0, 1, 0, P;\n\t}"
            : "=r"(done) : "r"(mb) : "memory");
        if (!done) {
            asm volatile(
                "{\n\t.reg .pred P;\n\t"
                "WL_%=:\n\t"
                "mbarrier.try_wait.parity.acquire.cta.shared::cta.b64 P, [%0], 0, 0x989680;\n\t"
                "@P bra.uni WD_%=;\n\t"
                "bra.uni WL_%=;\n\t"
                "WD_%=:\n\t}"
                :: "r"(mb) : "memory");
        }
    }

    const float4* __restrict__ Vs = (const float4*)&buf[wid][0];
    const float4* __restrict__ Ws = (const float4*)&buf[wid][ROW_BYTES];

    float acc[16];
#pragma unroll
    for (int k = 0; k < 16; k++) acc[k] = 0.0f;

#pragma unroll 1
    for (int k = 0; k < 9; k++) {               // d = lane + 32k, k=0..8 always < 300
        const int d = lane + 32 * k;
        const float4 v = Vs[d];
        const float4 w = Ws[d];
        acc[0]  = fmaf(w.x, v.x, acc[0]);
        acc[1]  = fmaf(w.x, v.y, acc[1]);
        acc[2]  = fmaf(w.x, v.z, acc[2]);
        acc[3]  = fmaf(w.x, v.w, acc[3]);
        acc[4]  = fmaf(w.y, v.x, acc[4]);
        acc[5]  = fmaf(w.y, v.y, acc[5]);
        acc[6]  = fmaf(w.y, v.z, acc[6]);
        acc[7]  = fmaf(w.y, v.w, acc[7]);
        acc[8]  = fmaf(w.z, v.x, acc[8]);
        acc[9]  = fmaf(w.z, v.y, acc[9]);
        acc[10] = fmaf(w.z, v.z, acc[10]);
        acc[11] = fmaf(w.z, v.w, acc[11]);
        acc[12] = fmaf(w.w, v.x, acc[12]);
        acc[13] = fmaf(w.w, v.y, acc[13]);
        acc[14] = fmaf(w.w, v.z, acc[14]);
        acc[15] = fmaf(w.w, v.w, acc[15]);
    }
    if (lane < 12) {                            // d = lane + 288 in [288, 299]
        const int d = lane + 288;
        const float4 v = Vs[d];
        const float4 w = Ws[d];
        acc[0]  = fmaf(w.x, v.x, acc[0]);
        acc[1]  = fmaf(w.x, v.y, acc[1]);
        acc[2]  = fmaf(w.x, v.z, acc[2]);
        acc[3]  = fmaf(w.x, v.w, acc[3]);
        acc[4]  = fmaf(w.y, v.x, acc[4]);
        acc[5]  = fmaf(w.y, v.y, acc[5]);
        acc[6]  = fmaf(w.y, v.z, acc[6]);
        acc[7]  = fmaf(w.y, v.w, acc[7]);
        acc[8]  = fmaf(w.z, v.x, acc[8]);
        acc[9]  = fmaf(w.z, v.y, acc[9]);
        acc[10] = fmaf(w.z, v.z, acc[10]);
        acc[11] = fmaf(w.z, v.w, acc[11]);
        acc[12] = fmaf(w.w, v.x, acc[12]);
        acc[13] = fmaf(w.w, v.y, acc[13]);
        acc[14] = fmaf(w.w, v.z, acc[14]);
        acc[15] = fmaf(w.w, v.w, acc[15]);
    }

#pragma unroll
    for (int off = 16; off > 0; off >>= 1) {
#pragma unroll
        for (int k = 0; k < 16; k++)
            acc[k] += __shfl_xor_sync(0xffffffffu, acc[k], off);
    }

    if (lane == 0) {
        const float4 wb = __ldg(wb4 + j);
        const float4 vb = __ldg(vb4 + i);
        const float bs[4] = {wb.x, wb.y, wb.z, wb.w};
        const float bt[4] = {vb.x, vb.y, vb.z, vb.w};

        float vals[16];
        float m = -INFINITY;
#pragma unroll
        for (int s = 0; s < 4; s++) {
#pragma unroll
            for (int t = 0; t < 4; t++) {
                const float x = acc[s * 4 + t] + bs[s] + bt[t];
                vals[s * 4 + t] = x;
                m = fmaxf(m, x);
            }
        }
        float sum = 0.0f;
#pragma unroll
        for (int k = 0; k < 16; k++)
            sum += __expf(vals[k] - m);
        out[p] = __logf(sum) + m;
    }
}

extern "C" void kernel_launch(void* const* d_in, const int* in_sizes, int n_in,
                              void* d_out, int out_size)
{
    const char* Vb        = (const char*)d_in[0];
    const char* Wb        = (const char*)d_in[1];
    const float4* vb4     = (const float4*)d_in[2];
    const float4* wb4     = (const float4*)d_in[3];
    const int* IJ         = (const int*)d_in[4];
    float* out            = (float*)d_out;

    const int B = in_sizes[4] / 2;

    void* counts_ptr = nullptr;
    cudaGetSymbolAddress(&counts_ptr, g_counts);
    cudaMemsetAsync(counts_ptr, 0, NBUCK * sizeof(int), 0);

    const int t = 256;
    count_kernel<<<(B + t - 1) / t, t>>>(IJ, B);
    scan_kernel<<<1, SCAN_T>>>();
    scatter_kernel<<<(B + t - 1) / t, t>>>(IJ, B);

    const int blocks = (B + WARPS_CTA - 1) / WARPS_CTA;
    multisense_kernel<<<blocks, WARPS_CTA * 32>>>(Vb, Wb, vb4, wb4, IJ, out, B);
}